// round 5
// baseline (speedup 1.0000x reference)
#include <cuda_runtime.h>

#define B_GRAPHS 64
#define D_IN     64
#define D_HID    128
#define D_OUT    128
#define TILE_N   64
#define TPB      256

// d_out layout (floats):
//   [0, 8192)      out      [B, D_OUT]
//   [8192, 8384)   pos_dst  [B, 3]
//   [8384, 8448)   batch[idx] as float [B]
//   [8448, 9024)   lframes_dst [B, 3, 3]
#define OFF_OUT   0
#define OFF_PD    8192
#define OFF_BV    8384
#define OFF_LF    8448

// ---------------- device scratch (no allocation allowed) ----------------
__device__ int          g_starts[B_GRAPHS + 1];
__device__ float        g_cg[B_GRAPHS * D_HID];
__device__ unsigned int g_umax[B_GRAPHS * D_OUT];

// ---------------- small helpers ----------------
__device__ __forceinline__ unsigned enc_max(float f) {
    unsigned u = __float_as_uint(f);
    return (u & 0x80000000u) ? ~u : (u | 0x80000000u);
}
__device__ __forceinline__ float dec_max(unsigned u) {
    if (u == 0u) return __int_as_float(0xff800000); // -inf (empty segment)
    return (u & 0x80000000u) ? __uint_as_float(u & 0x7fffffffu)
                             : __uint_as_float(~u);
}
__device__ __forceinline__ unsigned long long dup_f(float x) {
    unsigned long long r; unsigned u = __float_as_uint(x);
    asm("mov.b64 %0, {%1, %1};" : "=l"(r) : "r"(u));
    return r;
}
__device__ __forceinline__ void ffma2(unsigned long long& d,
                                      unsigned long long a,
                                      unsigned long long b) {
    asm("fma.rn.f32x2 %0, %1, %2, %0;" : "+l"(d) : "l"(a), "l"(b));
}
__device__ __forceinline__ float2 unpack2(unsigned long long v) {
    unsigned lo, hi;
    asm("mov.b64 {%0, %1}, %2;" : "=r"(lo), "=r"(hi) : "l"(v));
    return make_float2(__uint_as_float(lo), __uint_as_float(hi));
}

// ---------------- K0: init scratch ----------------
__global__ void k_init(int N) {
    int i = blockIdx.x * blockDim.x + threadIdx.x;
    if (i < B_GRAPHS * D_OUT) g_umax[i] = 0u;
    if (i < B_GRAPHS)  g_starts[i] = -1;
    if (i == B_GRAPHS) g_starts[B_GRAPHS] = N;
}

// ---------------- K1: segment boundaries (batch is sorted) ----------------
__global__ void k_bounds(const int* __restrict__ batch, int N) {
    int i = blockIdx.x * blockDim.x + threadIdx.x;
    if (i >= N) return;
    if (i == 0 || batch[i] != batch[i - 1]) g_starts[batch[i]] = i;
}

// ---------------- K2: fill empty-graph boundaries ----------------
__global__ void k_fill() {
    for (int g = B_GRAPHS - 1; g >= 0; --g)
        if (g_starts[g] < 0) g_starts[g] = g_starts[g + 1];
}

// ---------------- K3: per-graph COM, argmin, dst gathers, c_g ----------------
__global__ void k_graph(const float* __restrict__ x,
                        const float* __restrict__ pos,
                        const int*   __restrict__ batch,
                        const float* __restrict__ lf,
                        const float* __restrict__ W1,
                        const float* __restrict__ b1,
                        float* __restrict__ out, int N) {
    __shared__ float sx[TPB], sy[TPB], sz[TPB];
    __shared__ unsigned long long skey[TPB];
    __shared__ float scom[3], spd[3];
    __shared__ float sxd[D_IN];
    __shared__ int   sidx;

    const int g = blockIdx.x, tid = threadIdx.x;
    const int s = g_starts[g], e = g_starts[g + 1];
    const int count = e - s;

    // deterministic sum reduction (replay-stable)
    float fx = 0.f, fy = 0.f, fz = 0.f;
    for (int i = s + tid; i < e; i += TPB) {
        fx += pos[i * 3 + 0]; fy += pos[i * 3 + 1]; fz += pos[i * 3 + 2];
    }
    sx[tid] = fx; sy[tid] = fy; sz[tid] = fz;
    __syncthreads();
    for (int off = TPB / 2; off > 0; off >>= 1) {
        if (tid < off) { sx[tid] += sx[tid+off]; sy[tid] += sy[tid+off]; sz[tid] += sz[tid+off]; }
        __syncthreads();
    }
    if (tid == 0) {
        float c = (float)max(count, 1);
        scom[0] = sx[0] / c; scom[1] = sy[0] / c; scom[2] = sz[0] / c;
    }
    __syncthreads();

    // argmin distance, first-occurrence tie-break via (distbits<<32)|idx
    const float cx = scom[0], cy = scom[1], cz = scom[2];
    unsigned long long best = ~0ULL;
    for (int i = s + tid; i < e; i += TPB) {
        float dx = pos[i*3+0] - cx, dy = pos[i*3+1] - cy, dz = pos[i*3+2] - cz;
        float d = sqrtf(dx*dx + dy*dy + dz*dz);
        unsigned long long key = ((unsigned long long)__float_as_uint(d) << 32) | (unsigned)i;
        best = min(best, key);
    }
    skey[tid] = best;
    __syncthreads();
    for (int off = TPB / 2; off > 0; off >>= 1) {
        if (tid < off) skey[tid] = min(skey[tid], skey[tid + off]);
        __syncthreads();
    }
    if (tid == 0) sidx = (count == 0) ? (N - 1) : (int)(skey[0] & 0xffffffffu);
    __syncthreads();
    const int idx = sidx;

    if (tid < D_IN) sxd[tid] = x[idx * D_IN + tid];
    if (tid < 3) { spd[tid] = pos[idx * 3 + tid]; out[OFF_PD + g * 3 + tid] = spd[tid]; }
    if (tid == 0) out[OFF_BV + g] = (float)batch[idx];
    if (tid < 9)  out[OFF_LF + g * 9 + tid] = lf[idx * 9 + tid];
    __syncthreads();

    // c_g[j] = sum_k xd[k]*(W1[k][j]-W1[64+k][j]) - sum_t pd[t]*W1[128+t][j] + b1[j]
    if (tid < D_HID) {
        int j = tid;
        float acc = b1[j];
        #pragma unroll 4
        for (int k = 0; k < D_IN; ++k)
            acc += sxd[k] * (W1[k * D_HID + j] - W1[(D_IN + k) * D_HID + j]);
        #pragma unroll
        for (int t = 0; t < 3; ++t)
            acc -= spd[t] * W1[(2 * D_IN + t) * D_HID + j];
        g_cg[g * D_HID + j] = acc;
    }
}

// ---------------- shared-mem layout for main kernel (floats) ----------------
#define F_W1   0          // 67 x 128            = 8576
#define F_W2   8576       // 128 x 128           = 16384
#define F_H    24960      // 128 x 68 (pitch)    = 8704
#define F_U    33664      // max(67x68, 64x130)  = 8320
#define F_B2   41984      // 128
#define F_CG   42112      // 2 x 128
#define F_BID  42368      // 64 ints
#define F_G01  42432      // 2 ints
#define SMEM_FLOATS 42434
#define SMEM_BYTES  (SMEM_FLOATS * 4)

// microtile GEMM: 4 nodes x 8 channels (as 4 f32x2 pairs) per thread
__device__ __forceinline__ void gemm_tile(const float* __restrict__ pa,
                                          const float* __restrict__ pw,
                                          int K, unsigned long long acc[16]) {
    #pragma unroll 4
    for (int k = 0; k < K; ++k) {
        float4 a = *reinterpret_cast<const float4*>(pa + k * 68);
        ulonglong2 w01 = *reinterpret_cast<const ulonglong2*>(pw + k * 128);
        ulonglong2 w23 = *reinterpret_cast<const ulonglong2*>(pw + k * 128 + 4);
        unsigned long long a0 = dup_f(a.x), a1 = dup_f(a.y),
                           a2 = dup_f(a.z), a3 = dup_f(a.w);
        ffma2(acc[ 0], a0, w01.x); ffma2(acc[ 1], a0, w01.y);
        ffma2(acc[ 2], a0, w23.x); ffma2(acc[ 3], a0, w23.y);
        ffma2(acc[ 4], a1, w01.x); ffma2(acc[ 5], a1, w01.y);
        ffma2(acc[ 6], a1, w23.x); ffma2(acc[ 7], a1, w23.y);
        ffma2(acc[ 8], a2, w01.x); ffma2(acc[ 9], a2, w01.y);
        ffma2(acc[10], a2, w23.x); ffma2(acc[11], a2, w23.y);
        ffma2(acc[12], a3, w01.x); ffma2(acc[13], a3, w01.y);
        ffma2(acc[14], a3, w23.x); ffma2(acc[15], a3, w23.y);
    }
}

// ---------------- K4: main fused MLP + segment-max (persistent) ----------------
__global__ void __launch_bounds__(TPB, 1)
k_main(const float* __restrict__ x,
       const float* __restrict__ pos,
       const int*   __restrict__ batch,
       const float* __restrict__ W1,
       const float* __restrict__ W2,
       const float* __restrict__ b2,
       int N, int nTiles) {
    extern __shared__ float smem[];
    float* sW1 = smem + F_W1;
    float* sW2 = smem + F_W2;
    float* sH  = smem + F_H;
    float* sU  = smem + F_U;     // stage1: sInT[67][68]; stage3: sMsg[64][130]
    float* sb2 = smem + F_B2;
    float* sCg = smem + F_CG;    // 2 x 128
    int*   sB  = (int*)(smem + F_BID);
    int*   sG  = (int*)(smem + F_G01);

    const int tid = threadIdx.x;
    const int tc = tid & 15, tn = tid >> 4;
    const int cb = tc << 3, nb = tn << 2;

    // load resident weights: W1' rows = [W1[64:128] ; W1[128:131]]
    for (int q = tid; q < 67 * 32; q += TPB) {
        int row = q >> 5, c4 = q & 31;
        int srow = (row < 64) ? (64 + row) : (128 + (row - 64));
        reinterpret_cast<float4*>(sW1)[row * 32 + c4] =
            reinterpret_cast<const float4*>(W1)[srow * 32 + c4];
    }
    for (int q = tid; q < 128 * 32; q += TPB)
        reinterpret_cast<float4*>(sW2)[q] = reinterpret_cast<const float4*>(W2)[q];
    if (tid < D_OUT) sb2[tid] = b2[tid];
    __syncthreads();

    for (int tile = blockIdx.x; tile < nTiles; tile += gridDim.x) {
        const int node0 = tile * TILE_N;

        // ---- load x tile (transposed), pos rows, batch ids, c_g rows ----
        const float4* X4 = reinterpret_cast<const float4*>(x);
        for (int q = tid; q < TILE_N * 16; q += TPB) {
            int node = q >> 4, kq = q & 15;
            int gn = node0 + node;
            float4 v = (gn < N) ? X4[gn * 16 + kq] : make_float4(0.f, 0.f, 0.f, 0.f);
            int kb = kq << 2;
            sU[(kb + 0) * 68 + node] = v.x;
            sU[(kb + 1) * 68 + node] = v.y;
            sU[(kb + 2) * 68 + node] = v.z;
            sU[(kb + 3) * 68 + node] = v.w;
        }
        for (int q = tid; q < TILE_N * 3; q += TPB) {
            int node = q / 3, t = q - node * 3;
            int gn = node0 + node;
            sU[(64 + t) * 68 + node] = (gn < N) ? pos[gn * 3 + t] : 0.f;
        }
        if (tid < TILE_N) {
            int gn = node0 + tid;
            sB[tid] = (gn < N) ? batch[gn] : -1;
        }
        {   // stage the (<=2) graphs' c_g rows this tile touches
            int g0 = batch[node0];
            int g1 = batch[min(node0 + TILE_N - 1, N - 1)];
            if (tid == 0) { sG[0] = g0; sG[1] = g1; }
            if (tid < 128)       sCg[tid]       = g_cg[g0 * D_HID + tid];
            else                 sCg[tid]       = g_cg[g1 * D_HID + (tid - 128)];
        }
        __syncthreads();

        // ---- stage 1: y = x@W1b + pos@W1c ; h = relu(y + c_g) ----
        unsigned long long acc[16];
        #pragma unroll
        for (int i = 0; i < 16; ++i) acc[i] = 0ULL;
        gemm_tile(sU + nb, sW1 + cb, 67, acc);

        float h[4][8];
        const int g0 = sG[0], g1 = sG[1];
        #pragma unroll
        for (int j = 0; j < 4; ++j) {
            int g = sB[nb + j];
            const float* cgp;
            if (g == g0)      cgp = sCg;
            else if (g == g1) cgp = sCg + 128;
            else if (g >= 0)  cgp = g_cg + g * D_HID;
            else              cgp = sCg;   // pad node: value discarded later
            #pragma unroll
            for (int p = 0; p < 4; ++p) {
                float2 t = unpack2(acc[j * 4 + p]);
                h[j][2 * p]     = fmaxf(t.x + cgp[cb + 2 * p], 0.f);
                h[j][2 * p + 1] = fmaxf(t.y + cgp[cb + 2 * p + 1], 0.f);
            }
        }
        // store h transposed [channel][node], staggered to dodge bank conflicts
        #pragma unroll
        for (int cc = 0; cc < 8; ++cc) {
            int c = (cc + tc) & 7;
            *reinterpret_cast<float4*>(&sH[(cb + c) * 68 + nb]) =
                make_float4(h[0][c], h[1][c], h[2][c], h[3][c]);
        }
        __syncthreads();

        // ---- stage 2: msg = h@W2 + b2 ----
        #pragma unroll
        for (int i = 0; i < 16; ++i) acc[i] = 0ULL;
        gemm_tile(sH + nb, sW2 + cb, 128, acc);

        #pragma unroll
        for (int j = 0; j < 4; ++j) {
            int base = (nb + j) * 130 + cb;
            #pragma unroll
            for (int p = 0; p < 4; ++p) {
                float2 t = unpack2(acc[j * 4 + p]);
                sU[base + 2 * p]     = t.x + sb2[cb + 2 * p];
                sU[base + 2 * p + 1] = t.y + sb2[cb + 2 * p + 1];
            }
        }
        __syncthreads();

        // ---- stage 3: run-length segment max -> global atomicMax ----
        if (tid < D_OUT) {
            int curg = -1; float cur = 0.f;
            #pragma unroll 1
            for (int nd = 0; nd < TILE_N; ++nd) {
                int g = sB[nd];
                float v = sU[nd * 130 + tid];
                if (g != curg) {
                    if (curg >= 0)
                        atomicMax(&g_umax[curg * D_OUT + tid], enc_max(cur));
                    curg = g; cur = v;
                } else {
                    cur = fmaxf(cur, v);
                }
            }
            if (curg >= 0)
                atomicMax(&g_umax[curg * D_OUT + tid], enc_max(cur));
        }
        __syncthreads();
    }
}

// ---------------- K5: decode maxima into d_out ----------------
__global__ void k_out(float* __restrict__ out) {
    int i = blockIdx.x * blockDim.x + threadIdx.x;
    if (i < B_GRAPHS * D_OUT) out[OFF_OUT + i] = dec_max(g_umax[i]);
}

// ---------------- entry ----------------
extern "C" void kernel_launch(void* const* d_in, const int* in_sizes, int n_in,
                              void* d_out, int out_size) {
    const float* x     = (const float*)d_in[0];
    const float* pos   = (const float*)d_in[1];
    const int*   batch = (const int*)  d_in[2];
    const float* lf    = (const float*)d_in[3];
    const float* W1    = (const float*)d_in[4];
    const float* b1    = (const float*)d_in[5];
    const float* W2    = (const float*)d_in[6];
    const float* b2    = (const float*)d_in[7];
    float* out = (float*)d_out;

    const int N = in_sizes[2];
    const int nTiles = (N + TILE_N - 1) / TILE_N;

    int nsm = 148;
    cudaDeviceGetAttribute(&nsm, cudaDevAttrMultiProcessorCount, 0);
    if (nsm <= 0) nsm = 148;

    cudaFuncSetAttribute(k_main, cudaFuncAttributeMaxDynamicSharedMemorySize,
                         SMEM_BYTES);

    k_init  <<<(B_GRAPHS * D_OUT + TPB - 1) / TPB, TPB>>>(N);
    k_bounds<<<(N + TPB - 1) / TPB, TPB>>>(batch, N);
    k_fill  <<<1, 1>>>();
    k_graph <<<B_GRAPHS, TPB>>>(x, pos, batch, lf, W1, b1, out, N);
    k_main  <<<nsm, TPB, SMEM_BYTES>>>(x, pos, batch, W1, W2, b2, N, nTiles);
    k_out   <<<(B_GRAPHS * D_OUT + TPB - 1) / TPB, TPB>>>(out);
}

// round 7
// speedup vs baseline: 3.1078x; 3.1078x over previous
#include <cuda_runtime.h>

#define B_GRAPHS 64
#define D_IN     64
#define D_HID    128
#define D_OUT    128
#define TILE_M   128
#define TPB      256

// d_out layout (floats):
//   [0, 8192)      out      [B, D_OUT]
//   [8192, 8384)   pos_dst  [B, 3]
//   [8384, 8448)   batch[idx] as float [B]
//   [8448, 9024)   lframes_dst [B, 3, 3]
#define OFF_OUT   0
#define OFF_PD    8192
#define OFF_BV    8384
#define OFF_LF    8448

// ---------------- device scratch ----------------
__device__ int          g_starts[B_GRAPHS + 1];
__device__ float        g_cg[B_GRAPHS * D_HID];
__device__ unsigned int g_umax[B_GRAPHS * D_OUT];

// ---------------- helpers ----------------
__device__ __forceinline__ unsigned enc_max(float f) {
    unsigned u = __float_as_uint(f);
    return (u & 0x80000000u) ? ~u : (u | 0x80000000u);
}
__device__ __forceinline__ float dec_max(unsigned u) {
    if (u == 0u) return __int_as_float(0xff800000); // -inf (empty segment)
    return (u & 0x80000000u) ? __uint_as_float(u & 0x7fffffffu)
                             : __uint_as_float(~u);
}
// split (x0,x1) into packed bf16x2 hi + bf16x2 lo (x0 in low half)
__device__ __forceinline__ unsigned pack_hl(float x0, float x1, unsigned &lo) {
    unsigned hi;
    asm("cvt.rn.satfinite.bf16x2.f32 %0, %1, %2;" : "=r"(hi) : "f"(x1), "f"(x0));
    float h0 = __uint_as_float(hi << 16);
    float h1 = __uint_as_float(hi & 0xffff0000u);
    float r0 = x0 - h0, r1 = x1 - h1;   // exact residuals
    asm("cvt.rn.satfinite.bf16x2.f32 %0, %1, %2;" : "=r"(lo) : "f"(r1), "f"(r0));
    return hi;
}
__device__ __forceinline__ void mma_bf16(float d[4],
    unsigned a0, unsigned a1, unsigned a2, unsigned a3,
    unsigned b0, unsigned b1) {
    asm("mma.sync.aligned.m16n8k16.row.col.f32.bf16.bf16.f32 "
        "{%0,%1,%2,%3}, {%4,%5,%6,%7}, {%8,%9}, {%0,%1,%2,%3};"
        : "+f"(d[0]), "+f"(d[1]), "+f"(d[2]), "+f"(d[3])
        : "r"(a0), "r"(a1), "r"(a2), "r"(a3), "r"(b0), "r"(b1));
}

// ---------------- K0: init ----------------
__global__ void k_init(int N) {
    int i = blockIdx.x * blockDim.x + threadIdx.x;
    if (i < B_GRAPHS * D_OUT) g_umax[i] = 0u;
    if (i < B_GRAPHS)  g_starts[i] = -1;
    if (i == B_GRAPHS) g_starts[B_GRAPHS] = N;
}

// ---------------- K1: segment boundaries ----------------
__global__ void k_bounds(const int* __restrict__ batch, int N) {
    int i = blockIdx.x * blockDim.x + threadIdx.x;
    if (i >= N) return;
    if (i == 0 || batch[i] != batch[i - 1]) g_starts[batch[i]] = i;
}

// ---------------- K2: fill empty segments ----------------
__global__ void k_fill() {
    for (int g = B_GRAPHS - 1; g >= 0; --g)
        if (g_starts[g] < 0) g_starts[g] = g_starts[g + 1];
}

// ---------------- K3: COM, argmin, dst gathers, c_g (fp32, exact) -------
__global__ void k_graph(const float* __restrict__ x,
                        const float* __restrict__ pos,
                        const int*   __restrict__ batch,
                        const float* __restrict__ lf,
                        const float* __restrict__ W1,
                        const float* __restrict__ b1,
                        float* __restrict__ out, int N) {
    __shared__ float sx[TPB], sy[TPB], sz[TPB];
    __shared__ unsigned long long skey[TPB];
    __shared__ float scom[3], spd[3];
    __shared__ float sxd[D_IN];
    __shared__ int   sidx;

    const int g = blockIdx.x, tid = threadIdx.x;
    const int s = g_starts[g], e = g_starts[g + 1];
    const int count = e - s;

    float fx = 0.f, fy = 0.f, fz = 0.f;
    for (int i = s + tid; i < e; i += TPB) {
        fx += pos[i * 3 + 0]; fy += pos[i * 3 + 1]; fz += pos[i * 3 + 2];
    }
    sx[tid] = fx; sy[tid] = fy; sz[tid] = fz;
    __syncthreads();
    for (int off = TPB / 2; off > 0; off >>= 1) {
        if (tid < off) { sx[tid] += sx[tid+off]; sy[tid] += sy[tid+off]; sz[tid] += sz[tid+off]; }
        __syncthreads();
    }
    if (tid == 0) {
        float c = (float)max(count, 1);
        scom[0] = sx[0] / c; scom[1] = sy[0] / c; scom[2] = sz[0] / c;
    }
    __syncthreads();

    const float cx = scom[0], cy = scom[1], cz = scom[2];
    unsigned long long best = ~0ULL;
    for (int i = s + tid; i < e; i += TPB) {
        float dx = pos[i*3+0] - cx, dy = pos[i*3+1] - cy, dz = pos[i*3+2] - cz;
        float d = sqrtf(dx*dx + dy*dy + dz*dz);
        unsigned long long key = ((unsigned long long)__float_as_uint(d) << 32) | (unsigned)i;
        best = min(best, key);
    }
    skey[tid] = best;
    __syncthreads();
    for (int off = TPB / 2; off > 0; off >>= 1) {
        if (tid < off) skey[tid] = min(skey[tid], skey[tid + off]);
        __syncthreads();
    }
    if (tid == 0) sidx = (count == 0) ? (N - 1) : (int)(skey[0] & 0xffffffffu);
    __syncthreads();
    const int idx = sidx;

    if (tid < D_IN) sxd[tid] = x[idx * D_IN + tid];
    if (tid < 3) { spd[tid] = pos[idx * 3 + tid]; out[OFF_PD + g * 3 + tid] = spd[tid]; }
    if (tid == 0) out[OFF_BV + g] = (float)batch[idx];
    if (tid < 9)  out[OFF_LF + g * 9 + tid] = lf[idx * 9 + tid];
    __syncthreads();

    if (tid < D_HID) {
        int j = tid;
        float acc = b1[j];
        #pragma unroll 4
        for (int k = 0; k < D_IN; ++k)
            acc += sxd[k] * (W1[k * D_HID + j] - W1[(D_IN + k) * D_HID + j]);
        #pragma unroll
        for (int t = 0; t < 3; ++t)
            acc -= spd[t] * W1[(2 * D_IN + t) * D_HID + j];
        g_cg[g * D_HID + j] = acc;
    }
}

// ---------------- shared layout for k_main (u32 words) ----------------
#define P1   44    // word pitch, stage-1 operands (40 data words = 80 bf16)
#define P2   68    // word pitch, stage-2 operands (64 data words = 128 bf16)
#define MSGP 132   // float pitch of msg buffer
#define OW1H 0
#define OW1L 5632
#define OW2H 11264
#define OW2L 19968
#define OAH  28672
#define OAL  34304
#define OHH  39936
#define OHL  48640
#define OB2  57344
#define OCG  57472
#define OSB  57728
#define OSG  57856
#define SMEM_U32 57858
#define SMEM_BYTES (SMEM_U32 * 4)

template<int KSTEPS, int PITCH>
__device__ __forceinline__ void gemm_bf16(const unsigned* __restrict__ aH,
                                          const unsigned* __restrict__ aL,
                                          const unsigned* __restrict__ bH,
                                          const unsigned* __restrict__ bL,
                                          int r0, int qc, int ns,
                                          float acc[16][4]) {
    const unsigned* aHr = aH + r0 * PITCH + qc;
    const unsigned* aLr = aL + r0 * PITCH + qc;
    #pragma unroll
    for (int ks = 0; ks < KSTEPS; ++ks) {
        const int kb = ks * 8;
        unsigned a0h = aHr[kb],            a2h = aHr[kb + 4];
        unsigned a1h = aHr[kb + 8*PITCH],  a3h = aHr[kb + 8*PITCH + 4];
        unsigned a0l = aLr[kb],            a2l = aLr[kb + 4];
        unsigned a1l = aLr[kb + 8*PITCH],  a3l = aLr[kb + 8*PITCH + 4];
        #pragma unroll
        for (int j = 0; j < 16; ++j) {
            const unsigned* bh = bH + (j * 8 + ns) * PITCH + kb + qc;
            const unsigned* bl = bL + (j * 8 + ns) * PITCH + kb + qc;
            unsigned b0h = bh[0], b1h = bh[4];
            unsigned b0l = bl[0], b1l = bl[4];
            mma_bf16(acc[j], a0h, a1h, a2h, a3h, b0h, b1h);
            mma_bf16(acc[j], a0l, a1l, a2l, a3l, b0h, b1h);
            mma_bf16(acc[j], a0h, a1h, a2h, a3h, b0l, b1l);
        }
    }
}

// ---------------- K4: fused MLP + segment-max, tensor-core ----------------
__global__ void __launch_bounds__(TPB, 1)
k_main(const float* __restrict__ x,
       const float* __restrict__ pos,
       const int*   __restrict__ batch,
       const float* __restrict__ W1,
       const float* __restrict__ W2,
       const float* __restrict__ b2,
       int N, int nTiles) {
    extern __shared__ unsigned sm[];
    float* smf = (float*)sm;
    int*   smi = (int*)sm;

    const int tid  = threadIdx.x;
    const int lane = tid & 31;
    const int warp = tid >> 5;
    const int r0   = (warp << 4) + (lane >> 2);  // this thread's M-rows: r0, r0+8
    const int qc   = lane & 3;
    const int ns   = lane >> 2;

    // ---- one-time: split weights into bf16 hi/lo, B-layout [n][k] ----
    for (int q = tid; q < 128 * 40; q += TPB) {
        int n = q / 40, kw = q - n * 40;
        int k0 = kw * 2, k1 = k0 + 1;
        float f0 = (k0 < 64) ? W1[(64 + k0) * D_HID + n]
                 : (k0 < 67) ? W1[(128 + k0 - 64) * D_HID + n] : 0.f;
        float f1 = (k1 < 64) ? W1[(64 + k1) * D_HID + n]
                 : (k1 < 67) ? W1[(128 + k1 - 64) * D_HID + n] : 0.f;
        unsigned lo, hi = pack_hl(f0, f1, lo);
        sm[OW1H + n * P1 + kw] = hi;
        sm[OW1L + n * P1 + kw] = lo;
    }
    for (int q = tid; q < 128 * 64; q += TPB) {
        int n = q >> 6, kw = q & 63;
        float f0 = W2[(2 * kw)     * D_OUT + n];
        float f1 = W2[(2 * kw + 1) * D_OUT + n];
        unsigned lo, hi = pack_hl(f0, f1, lo);
        sm[OW2H + n * P2 + kw] = hi;
        sm[OW2L + n * P2 + kw] = lo;
    }
    if (tid < D_OUT) smf[OB2 + tid] = b2[tid];
    // zero A pad words (k = 68..79 -> words 34..39), written once
    for (int q = tid; q < 128 * 6; q += TPB) {
        int node = q / 6, wi = q - node * 6;
        sm[OAH + node * P1 + 34 + wi] = 0;
        sm[OAL + node * P1 + 34 + wi] = 0;
    }
    __syncthreads();

    const float4* X4 = (const float4*)x;

    for (int tile = blockIdx.x; tile < nTiles; tile += gridDim.x) {
        const int node0 = tile * TILE_M;

        // ---- load + split A tile ----
        for (int q = tid; q < TILE_M * 16; q += TPB) {
            int node = q >> 4, kq = q & 15, gn = node0 + node;
            float4 v = make_float4(0.f, 0.f, 0.f, 0.f);
            if (gn < N) v = X4[gn * 16 + kq];
            unsigned l0, l1;
            unsigned h0 = pack_hl(v.x, v.y, l0);
            unsigned h1 = pack_hl(v.z, v.w, l1);
            int base = node * P1 + kq * 2;
            *(uint2*)&sm[OAH + base] = make_uint2(h0, h1);
            *(uint2*)&sm[OAL + base] = make_uint2(l0, l1);
        }
        if (tid < TILE_M) {
            int node = tid, gn = node0 + node;
            float p0 = 0.f, p1 = 0.f, p2 = 0.f; int g = -1;
            if (gn < N) { p0 = pos[gn*3]; p1 = pos[gn*3+1]; p2 = pos[gn*3+2]; g = batch[gn]; }
            unsigned l0, l1;
            unsigned h0 = pack_hl(p0, p1, l0);
            unsigned h1 = pack_hl(p2, 0.f, l1);
            sm[OAH + node * P1 + 32] = h0; sm[OAH + node * P1 + 33] = h1;
            sm[OAL + node * P1 + 32] = l0; sm[OAL + node * P1 + 33] = l1;
            smi[OSB + node] = g;
        }
        {
            int gF = batch[node0];
            if (tid == 0) smi[OSG] = gF;
            int g2 = min(gF + 1, B_GRAPHS - 1);
            if (tid < 128) smf[OCG + tid] = g_cg[gF * D_HID + tid];
            else           smf[OCG + tid] = g_cg[g2 * D_HID + (tid - 128)];
        }
        __syncthreads();

        // ---- stage 1: y = x@W1b + pos@W1c (split-bf16, 3 passes) ----
        float acc[16][4];
        #pragma unroll
        for (int j = 0; j < 16; ++j)
            acc[j][0] = acc[j][1] = acc[j][2] = acc[j][3] = 0.f;
        gemm_bf16<5, P1>(sm + OAH, sm + OAL, sm + OW1H, sm + OW1L, r0, qc, ns, acc);

        // epilogue 1: + c_g, relu, split to bf16 hi/lo into H
        {
            const int gF = smi[OSG];
            int gA = smi[OSB + r0];
            int gB = smi[OSB + r0 + 8];
            const float* cgA = (gA == gF)     ? (smf + OCG)
                             : (gA == gF + 1) ? (smf + OCG + 128)
                             : (gA >= 0)      ? (g_cg + gA * D_HID)
                                              : (smf + OCG);
            const float* cgB = (gB == gF)     ? (smf + OCG)
                             : (gB == gF + 1) ? (smf + OCG + 128)
                             : (gB >= 0)      ? (g_cg + gB * D_HID)
                                              : (smf + OCG);
            #pragma unroll
            for (int j = 0; j < 16; ++j) {
                int col = j * 8 + 2 * qc;
                float v0 = fmaxf(acc[j][0] + cgA[col],     0.f);
                float v1 = fmaxf(acc[j][1] + cgA[col + 1], 0.f);
                float v2 = fmaxf(acc[j][2] + cgB[col],     0.f);
                float v3 = fmaxf(acc[j][3] + cgB[col + 1], 0.f);
                unsigned l01, l23;
                unsigned h01 = pack_hl(v0, v1, l01);
                unsigned h23 = pack_hl(v2, v3, l23);
                int w = j * 4 + qc;
                sm[OHH + r0 * P2 + w]       = h01;
                sm[OHL + r0 * P2 + w]       = l01;
                sm[OHH + (r0 + 8) * P2 + w] = h23;
                sm[OHL + (r0 + 8) * P2 + w] = l23;
            }
        }
        __syncthreads();

        // ---- stage 2: msg = h@W2 ----
        #pragma unroll
        for (int j = 0; j < 16; ++j)
            acc[j][0] = acc[j][1] = acc[j][2] = acc[j][3] = 0.f;
        gemm_bf16<8, P2>(sm + OHH, sm + OHL, sm + OW2H, sm + OW2L, r0, qc, ns, acc);
        __syncthreads();   // all warps done reading H before overwrite

        // epilogue 2: + b2, write fp32 msg into H region
        {
            float* msg = (float*)(sm + OHH);
            #pragma unroll
            for (int j = 0; j < 16; ++j) {
                int col = j * 8 + 2 * qc;
                float bb0 = smf[OB2 + col], bb1 = smf[OB2 + col + 1];
                *(float2*)&msg[r0 * MSGP + col] =
                    make_float2(acc[j][0] + bb0, acc[j][1] + bb1);
                *(float2*)&msg[(r0 + 8) * MSGP + col] =
                    make_float2(acc[j][2] + bb0, acc[j][3] + bb1);
            }
        }
        __syncthreads();

        // ---- stage 3: run-length segment max -> global atomicMax ----
        {
            const float* msg = (const float*)(sm + OHH);
            int ch = tid & 127, half = tid >> 7;
            int nd0 = half * 64, nd1 = nd0 + 64;
            int curg = -1; float cur = 0.f;
            #pragma unroll 1
            for (int nd = nd0; nd < nd1; ++nd) {
                int g = smi[OSB + nd];
                float v = msg[nd * MSGP + ch];
                if (g != curg) {
                    if (curg >= 0)
                        atomicMax(&g_umax[curg * D_OUT + ch], enc_max(cur));
                    curg = g; cur = v;
                } else {
                    cur = fmaxf(cur, v);
                }
            }
            if (curg >= 0)
                atomicMax(&g_umax[curg * D_OUT + ch], enc_max(cur));
        }
        __syncthreads();
    }
}

// ---------------- K5: decode maxima ----------------
__global__ void k_out(float* __restrict__ out) {
    int i = blockIdx.x * blockDim.x + threadIdx.x;
    if (i < B_GRAPHS * D_OUT) out[OFF_OUT + i] = dec_max(g_umax[i]);
}

// ---------------- entry ----------------
extern "C" void kernel_launch(void* const* d_in, const int* in_sizes, int n_in,
                              void* d_out, int out_size) {
    const float* x     = (const float*)d_in[0];
    const float* pos   = (const float*)d_in[1];
    const int*   batch = (const int*)  d_in[2];
    const float* lf    = (const float*)d_in[3];
    const float* W1    = (const float*)d_in[4];
    const float* b1    = (const float*)d_in[5];
    const float* W2    = (const float*)d_in[6];
    const float* b2    = (const float*)d_in[7];
    float* out = (float*)d_out;

    const int N = in_sizes[2];
    const int nTiles = (N + TILE_M - 1) / TILE_M;

    int nsm = 148;
    cudaDeviceGetAttribute(&nsm, cudaDevAttrMultiProcessorCount, 0);
    if (nsm <= 0) nsm = 148;

    cudaFuncSetAttribute(k_main, cudaFuncAttributeMaxDynamicSharedMemorySize,
                         SMEM_BYTES);

    k_init  <<<(B_GRAPHS * D_OUT + TPB - 1) / TPB, TPB>>>(N);
    k_bounds<<<(N + TPB - 1) / TPB, TPB>>>(batch, N);
    k_fill  <<<1, 1>>>();
    k_graph <<<B_GRAPHS, TPB>>>(x, pos, batch, lf, W1, b1, out, N);
    k_main  <<<nsm, TPB, SMEM_BYTES>>>(x, pos, batch, W1, W2, b2, N, nTiles);
    k_out   <<<(B_GRAPHS * D_OUT + TPB - 1) / TPB, TPB>>>(out);
}

// round 10
// speedup vs baseline: 4.7457x; 1.5270x over previous
#include <cuda_runtime.h>

#define B_GRAPHS 64
#define D_IN     64
#define D_HID    128
#define D_OUT    128
#define TILE_M   128
#define TPB      256

// d_out layout (floats):
//   [0, 8192)      out      [B, D_OUT]
//   [8192, 8384)   pos_dst  [B, 3]
//   [8384, 8448)   batch[idx] as float [B]
//   [8448, 9024)   lframes_dst [B, 3, 3]
#define OFF_OUT   0
#define OFF_PD    8192
#define OFF_BV    8384
#define OFF_LF    8448

// ---------------- device scratch ----------------
__device__ int          g_starts[B_GRAPHS + 1];
__device__ float        g_cg[B_GRAPHS * D_HID];
__device__ unsigned int g_umax[B_GRAPHS * D_OUT];

// ---------------- helpers ----------------
__device__ __forceinline__ unsigned enc_max(float f) {
    unsigned u = __float_as_uint(f);
    return (u & 0x80000000u) ? ~u : (u | 0x80000000u);
}
__device__ __forceinline__ float dec_max(unsigned u) {
    if (u == 0u) return __int_as_float(0xff800000); // -inf (empty segment)
    return (u & 0x80000000u) ? __uint_as_float(u & 0x7fffffffu)
                             : __uint_as_float(~u);
}
// split (x0,x1) into packed bf16x2 hi + bf16x2 lo (x0 in low half)
__device__ __forceinline__ unsigned pack_hl(float x0, float x1, unsigned &lo) {
    unsigned hi;
    asm("cvt.rn.satfinite.bf16x2.f32 %0, %1, %2;" : "=r"(hi) : "f"(x1), "f"(x0));
    float h0 = __uint_as_float(hi << 16);
    float h1 = __uint_as_float(hi & 0xffff0000u);
    float r0 = x0 - h0, r1 = x1 - h1;   // exact residuals
    asm("cvt.rn.satfinite.bf16x2.f32 %0, %1, %2;" : "=r"(lo) : "f"(r1), "f"(r0));
    return hi;
}
__device__ __forceinline__ void mma_bf16(float d[4],
    unsigned a0, unsigned a1, unsigned a2, unsigned a3,
    unsigned b0, unsigned b1) {
    asm("mma.sync.aligned.m16n8k16.row.col.f32.bf16.bf16.f32 "
        "{%0,%1,%2,%3}, {%4,%5,%6,%7}, {%8,%9}, {%0,%1,%2,%3};"
        : "+f"(d[0]), "+f"(d[1]), "+f"(d[2]), "+f"(d[3])
        : "r"(a0), "r"(a1), "r"(a2), "r"(a3), "r"(b0), "r"(b1));
}

// ---------------- K0: init ----------------
__global__ void k_init(int N) {
    int i = blockIdx.x * blockDim.x + threadIdx.x;
    if (i < B_GRAPHS * D_OUT) g_umax[i] = 0u;
    if (i < B_GRAPHS)  g_starts[i] = -1;
    if (i == B_GRAPHS) g_starts[B_GRAPHS] = N;
}

// ---------------- K1: segment boundaries ----------------
__global__ void k_bounds(const int* __restrict__ batch, int N) {
    int i = blockIdx.x * blockDim.x + threadIdx.x;
    if (i >= N) return;
    if (i == 0 || batch[i] != batch[i - 1]) g_starts[batch[i]] = i;
}

// ---------------- K2: fill empty segments ----------------
__global__ void k_fill() {
    for (int g = B_GRAPHS - 1; g >= 0; --g)
        if (g_starts[g] < 0) g_starts[g] = g_starts[g + 1];
}

// ---------------- K3: COM, argmin, dst gathers, c_g (fp32, exact) -------
__global__ void k_graph(const float* __restrict__ x,
                        const float* __restrict__ pos,
                        const int*   __restrict__ batch,
                        const float* __restrict__ lf,
                        const float* __restrict__ W1,
                        const float* __restrict__ b1,
                        float* __restrict__ out, int N) {
    __shared__ float sx[TPB], sy[TPB], sz[TPB];
    __shared__ unsigned long long skey[TPB];
    __shared__ float scom[3], spd[3];
    __shared__ float sxd[D_IN];
    __shared__ int   sidx;

    const int g = blockIdx.x, tid = threadIdx.x;
    const int s = g_starts[g], e = g_starts[g + 1];
    const int count = e - s;

    float fx = 0.f, fy = 0.f, fz = 0.f;
    for (int i = s + tid; i < e; i += TPB) {
        fx += pos[i * 3 + 0]; fy += pos[i * 3 + 1]; fz += pos[i * 3 + 2];
    }
    sx[tid] = fx; sy[tid] = fy; sz[tid] = fz;
    __syncthreads();
    for (int off = TPB / 2; off > 0; off >>= 1) {
        if (tid < off) { sx[tid] += sx[tid+off]; sy[tid] += sy[tid+off]; sz[tid] += sz[tid+off]; }
        __syncthreads();
    }
    if (tid == 0) {
        float c = (float)max(count, 1);
        scom[0] = sx[0] / c; scom[1] = sy[0] / c; scom[2] = sz[0] / c;
    }
    __syncthreads();

    const float cx = scom[0], cy = scom[1], cz = scom[2];
    unsigned long long best = ~0ULL;
    for (int i = s + tid; i < e; i += TPB) {
        float dx = pos[i*3+0] - cx, dy = pos[i*3+1] - cy, dz = pos[i*3+2] - cz;
        float d = sqrtf(dx*dx + dy*dy + dz*dz);
        unsigned long long key = ((unsigned long long)__float_as_uint(d) << 32) | (unsigned)i;
        best = min(best, key);
    }
    skey[tid] = best;
    __syncthreads();
    for (int off = TPB / 2; off > 0; off >>= 1) {
        if (tid < off) skey[tid] = min(skey[tid], skey[tid + off]);
        __syncthreads();
    }
    if (tid == 0) sidx = (count == 0) ? (N - 1) : (int)(skey[0] & 0xffffffffu);
    __syncthreads();
    const int idx = sidx;

    if (tid < D_IN) sxd[tid] = x[idx * D_IN + tid];
    if (tid < 3) { spd[tid] = pos[idx * 3 + tid]; out[OFF_PD + g * 3 + tid] = spd[tid]; }
    if (tid == 0) out[OFF_BV + g] = (float)batch[idx];
    if (tid < 9)  out[OFF_LF + g * 9 + tid] = lf[idx * 9 + tid];
    __syncthreads();

    if (tid < D_HID) {
        int j = tid;
        float acc = b1[j];
        #pragma unroll 4
        for (int k = 0; k < D_IN; ++k)
            acc += sxd[k] * (W1[k * D_HID + j] - W1[(D_IN + k) * D_HID + j]);
        #pragma unroll
        for (int t = 0; t < 3; ++t)
            acc -= spd[t] * W1[(2 * D_IN + t) * D_HID + j];
        g_cg[g * D_HID + j] = acc;
    }
}

// ---------------- shared layout for k_main (32-bit word offsets) --------
// W1frag: [n=128][ks=5][qc=4] uint4 {b0h,b1h,b0l,b1l}  = 10240 words
// W2frag: [n=128][ks-slot=9][qc=4] uint4 (8 used)       = 18432 words
// AfragH: [wb=8][ks=5][lane=32] uint4 {a0,a1,a2,a3}     =  5120 words
// AfragL: same                                          =  5120 words
#define OW1   0
#define OW2   10240
#define OAH   28672
#define OAL   33792
#define OB2   38912
#define OCG   39040
#define OSB   39296
#define OACC  39424
#define SMEM_U32 39552
#define SMEM_BYTES (SMEM_U32 * 4)

// ---------------- K4: fused MLP + segment-max, tensor-core v3 -----------
__global__ void __launch_bounds__(TPB, 1)
k_main(const float* __restrict__ x,
       const float* __restrict__ pos,
       const int*   __restrict__ batch,
       const float* __restrict__ W1,
       const float* __restrict__ W2,
       const float* __restrict__ b2,
       int N, int nTiles) {
    extern __shared__ unsigned sm[];
    uint4* sm4 = (uint4*)sm;
    float* smf = (float*)sm;
    int*   smi = (int*)sm;

    const int tid  = threadIdx.x;
    const int lane = tid & 31;
    const int warp = tid >> 5;
    const int qc   = lane & 3;
    const int ns   = lane >> 2;
    const int r0   = (warp << 4) + ns;   // rows r0, r0+8 within tile

    // ---- one-time: W1 fragments (rows: [W1[64:128]; W1[128:131]; pad]) ----
    for (int q = tid; q < 128 * 5 * 4; q += TPB) {
        int n = q / 20, rem = q % 20, ks = rem >> 2, qw = rem & 3;
        int kw0 = ks * 8 + qw, kw1 = kw0 + 4;
        float f[4];
        #pragma unroll
        for (int t = 0; t < 4; ++t) {
            int k = (t < 2) ? (2 * kw0 + t) : (2 * kw1 + (t - 2));
            f[t] = (k < 64) ? W1[(64 + k) * D_HID + n]
                 : (k < 67) ? W1[(128 + (k - 64)) * D_HID + n] : 0.f;
        }
        unsigned l0, h0 = pack_hl(f[0], f[1], l0);
        unsigned l1, h1 = pack_hl(f[2], f[3], l1);
        sm4[OW1 / 4 + q] = make_uint4(h0, h1, l0, l1);
    }
    // ---- one-time: W2 fragments ----
    for (int q = tid; q < 128 * 8 * 4; q += TPB) {
        int n = q >> 5, rem = q & 31, ks = rem >> 2, qw = rem & 3;
        int kw0 = ks * 8 + qw, kw1 = kw0 + 4;
        float f00 = W2[(2 * kw0)     * D_OUT + n];
        float f01 = W2[(2 * kw0 + 1) * D_OUT + n];
        float f10 = W2[(2 * kw1)     * D_OUT + n];
        float f11 = W2[(2 * kw1 + 1) * D_OUT + n];
        unsigned l0, h0 = pack_hl(f00, f01, l0);
        unsigned l1, h1 = pack_hl(f10, f11, l1);
        sm4[OW2 / 4 + (n * 9 + ks) * 4 + qw] = make_uint4(h0, h1, l0, l1);
    }
    if (tid < D_OUT) smf[OB2 + tid] = b2[tid];
    // ---- one-time: zero ks=4 A region (pos writes touch only x,y of qw 0,1)
    {
        int wb = tid >> 5, ln = tid & 31;   // 256 threads = 8x32 exactly
        sm4[OAH / 4 + (wb * 5 + 4) * 32 + ln] = make_uint4(0, 0, 0, 0);
        sm4[OAL / 4 + (wb * 5 + 4) * 32 + ln] = make_uint4(0, 0, 0, 0);
    }
    if (tid < 128) sm[OACC + tid] = 0u;
    __syncthreads();

    const float4* X4 = (const float4*)x;
    const int tpc = (nTiles + gridDim.x - 1) / gridDim.x;
    const int t0  = blockIdx.x * tpc;
    const int t1  = min(t0 + tpc, nTiles);

    float4 xv[8];
    float  pp0 = 0.f, pp1 = 0.f, pp2 = 0.f;
    int    pb = -1, pgF = 0;
    float  cg0 = 0.f, cg1 = 0.f;

#define PREFETCH(T) do {                                                     \
    int node0_ = (T) * TILE_M;                                               \
    _Pragma("unroll")                                                        \
    for (int i_ = 0; i_ < 8; ++i_) {                                         \
        int q_ = tid + i_ * TPB; int nd_ = q_ >> 4, kq_ = q_ & 15;           \
        int gn_ = node0_ + nd_;                                              \
        xv[i_] = (gn_ < N) ? X4[gn_ * 16 + kq_]                              \
                           : make_float4(0.f, 0.f, 0.f, 0.f);                \
    }                                                                        \
    pgF = batch[node0_];                                                     \
    if (tid < TILE_M) {                                                      \
        int gn_ = node0_ + tid;                                              \
        if (gn_ < N) { pp0 = pos[gn_*3]; pp1 = pos[gn_*3+1];                 \
                       pp2 = pos[gn_*3+2]; pb = batch[gn_]; }                \
        else { pp0 = pp1 = pp2 = 0.f; pb = -1; }                             \
    }                                                                        \
    if (tid < 128) {                                                         \
        int g2_ = min(pgF + 1, B_GRAPHS - 1);                                \
        cg0 = g_cg[pgF * D_HID + tid];                                       \
        cg1 = g_cg[g2_ * D_HID + tid];                                       \
    }                                                                        \
} while (0)

    if (t0 < t1) PREFETCH(t0);
    int accG = -1;

    for (int tile = t0; tile < t1; ++tile) {
        __syncthreads();   // prev tile's Afrag reads + sAcc ATOMS complete

        // ---- flush per-CTA accumulator on graph change ----
        if (pgF != accG) {
            if (accG >= 0 && tid < 128)
                atomicMax(&g_umax[accG * D_OUT + tid], sm[OACC + tid]);
            if (tid < 128) sm[OACC + tid] = 0u;
            accG = pgF;
        }

        // ---- STS: scatter prefetched tile into fragment layout ----
        #pragma unroll
        for (int i = 0; i < 8; ++i) {
            int q = tid + i * TPB; int nd = q >> 4, kq = q & 15;
            int wb = nd >> 4, lr = nd & 7, rb = (nd >> 3) & 1;
            int kw0 = 2 * kq;
            int ks = kw0 >> 3, w0 = kw0 & 7;
            int slot = (w0 >> 2) * 2 + rb;
            int idx4 = (wb * 5 + ks) * 32 + lr * 4 + (w0 & 3);
            unsigned lo0, hi0 = pack_hl(xv[i].x, xv[i].y, lo0);
            sm[OAH + idx4 * 4 + slot] = hi0;
            sm[OAL + idx4 * 4 + slot] = lo0;
            unsigned lo1, hi1 = pack_hl(xv[i].z, xv[i].w, lo1);
            sm[OAH + (idx4 + 1) * 4 + slot] = hi1;
            sm[OAL + (idx4 + 1) * 4 + slot] = lo1;
        }
        if (tid < TILE_M) {
            int nd = tid, wb = nd >> 4, lr = nd & 7, rb = (nd >> 3) & 1;
            int base4 = (wb * 5 + 4) * 32 + lr * 4;
            unsigned lo0, hi0 = pack_hl(pp0, pp1, lo0);
            sm[OAH + (base4 + 0) * 4 + rb] = hi0;
            sm[OAL + (base4 + 0) * 4 + rb] = lo0;
            unsigned lo1, hi1 = pack_hl(pp2, 0.f, lo1);
            sm[OAH + (base4 + 1) * 4 + rb] = hi1;
            sm[OAL + (base4 + 1) * 4 + rb] = lo1;
            smi[OSB + nd] = pb;
        }
        if (tid < 128) { smf[OCG + tid] = cg0; smf[OCG + 128 + tid] = cg1; }
        const int gFirst = pgF;
        __syncthreads();   // publish tile data + flush/reset

        if (tile + 1 < t1) PREFETCH(tile + 1);   // overlap next tile's LDG

        // ---- stage 1: y = x@W1b + pos@W1c (3-pass split bf16) ----
        float acc[16][4];
        #pragma unroll
        for (int j = 0; j < 16; ++j)
            acc[j][0] = acc[j][1] = acc[j][2] = acc[j][3] = 0.f;
        #pragma unroll
        for (int ks = 0; ks < 5; ++ks) {
            uint4 aH = sm4[OAH / 4 + (warp * 5 + ks) * 32 + lane];
            uint4 aL = sm4[OAL / 4 + (warp * 5 + ks) * 32 + lane];
            #pragma unroll
            for (int j = 0; j < 16; ++j) {
                uint4 b = sm4[OW1 / 4 + ((j * 8 + ns) * 5 + ks) * 4 + qc];
                mma_bf16(acc[j], aH.x, aH.y, aH.z, aH.w, b.x, b.y);
                mma_bf16(acc[j], aL.x, aL.y, aL.z, aL.w, b.x, b.y);
                mma_bf16(acc[j], aH.x, aH.y, aH.z, aH.w, b.z, b.w);
            }
        }

        // ---- epilogue 1: +c_g, relu, repack to stage-2 A frags (registers)
        const int gA  = smi[OSB + r0];
        const int gB  = smi[OSB + r0 + 8];
        const int gLo = smi[OSB + (warp << 4)];
        const int gHi = smi[OSB + (warp << 4) + 15];
        const float* cgA = (gA == gFirst)     ? (smf + OCG)
                         : (gA == gFirst + 1) ? (smf + OCG + 128)
                         : (gA >= 0)          ? (g_cg + gA * D_HID)
                                              : (smf + OCG);
        const float* cgB = (gB == gFirst)     ? (smf + OCG)
                         : (gB == gFirst + 1) ? (smf + OCG + 128)
                         : (gB >= 0)          ? (g_cg + gB * D_HID)
                                              : (smf + OCG);
        unsigned ah[8][4], al[8][4];
        #pragma unroll
        for (int j = 0; j < 16; ++j) {
            int col = j * 8 + 2 * qc;
            float v0 = fmaxf(acc[j][0] + cgA[col],     0.f);
            float v1 = fmaxf(acc[j][1] + cgA[col + 1], 0.f);
            float v2 = fmaxf(acc[j][2] + cgB[col],     0.f);
            float v3 = fmaxf(acc[j][3] + cgB[col + 1], 0.f);
            unsigned l01, h01 = pack_hl(v0, v1, l01);
            unsigned l23, h23 = pack_hl(v2, v3, l23);
            int k2 = j >> 1, off = (j & 1) * 2;
            ah[k2][off]     = h01;  al[k2][off]     = l01;
            ah[k2][off + 1] = h23;  al[k2][off + 1] = l23;
        }

        // ---- stage 2: msg = h@W2 (A in registers) ----
        float a2c[16][4];
        #pragma unroll
        for (int j = 0; j < 16; ++j)
            a2c[j][0] = a2c[j][1] = a2c[j][2] = a2c[j][3] = 0.f;
        #pragma unroll
        for (int ks = 0; ks < 8; ++ks) {
            #pragma unroll
            for (int j = 0; j < 16; ++j) {
                uint4 b = sm4[OW2 / 4 + ((j * 8 + ns) * 9 + ks) * 4 + qc];
                mma_bf16(a2c[j], ah[ks][0], ah[ks][1], ah[ks][2], ah[ks][3], b.x, b.y);
                mma_bf16(a2c[j], al[ks][0], al[ks][1], al[ks][2], al[ks][3], b.x, b.y);
                mma_bf16(a2c[j], ah[ks][0], ah[ks][1], ah[ks][2], ah[ks][3], b.z, b.w);
            }
        }

        // ---- stage 3: +b2, segment max (register path) ----
        if (gLo == gHi && gLo == accG) {
            // fast: warp's 16 rows all in accumulator graph
            float m0a[16], m1a[16];
            #pragma unroll
            for (int j = 0; j < 16; ++j) {
                int col = j * 8 + 2 * qc;
                float b0v = smf[OB2 + col], b1v = smf[OB2 + col + 1];
                m0a[j] = fmaxf(a2c[j][0] + b0v, a2c[j][2] + b0v);
                m1a[j] = fmaxf(a2c[j][1] + b1v, a2c[j][3] + b1v);
            }
            #pragma unroll
            for (int d = 4; d <= 16; d <<= 1) {
                #pragma unroll
                for (int j = 0; j < 16; ++j) {
                    m0a[j] = fmaxf(m0a[j], __shfl_xor_sync(0xffffffffu, m0a[j], d));
                    m1a[j] = fmaxf(m1a[j], __shfl_xor_sync(0xffffffffu, m1a[j], d));
                }
            }
            if (lane < 4) {
                #pragma unroll
                for (int j = 0; j < 16; ++j) {
                    int col = j * 8 + 2 * qc;
                    atomicMax(&sm[OACC + col],     enc_max(m0a[j]));
                    atomicMax(&sm[OACC + col + 1], enc_max(m1a[j]));
                }
            }
        } else {
            // slow: boundary / mixed / pad rows -> direct global atomics
            #pragma unroll
            for (int j = 0; j < 16; ++j) {
                int col = j * 8 + 2 * qc;
                float b0v = smf[OB2 + col], b1v = smf[OB2 + col + 1];
                if (gA >= 0) {
                    atomicMax(&g_umax[gA * D_OUT + col],     enc_max(a2c[j][0] + b0v));
                    atomicMax(&g_umax[gA * D_OUT + col + 1], enc_max(a2c[j][1] + b1v));
                }
                if (gB >= 0) {
                    atomicMax(&g_umax[gB * D_OUT + col],     enc_max(a2c[j][2] + b0v));
                    atomicMax(&g_umax[gB * D_OUT + col + 1], enc_max(a2c[j][3] + b1v));
                }
            }
        }
    }

    __syncthreads();
    if (accG >= 0 && tid < 128)
        atomicMax(&g_umax[accG * D_OUT + tid], sm[OACC + tid]);
#undef PREFETCH
}

// ---------------- K5: decode maxima ----------------
__global__ void k_out(float* __restrict__ out) {
    int i = blockIdx.x * blockDim.x + threadIdx.x;
    if (i < B_GRAPHS * D_OUT) out[OFF_OUT + i] = dec_max(g_umax[i]);
}

// ---------------- entry ----------------
extern "C" void kernel_launch(void* const* d_in, const int* in_sizes, int n_in,
                              void* d_out, int out_size) {
    const float* x     = (const float*)d_in[0];
    const float* pos   = (const float*)d_in[1];
    const int*   batch = (const int*)  d_in[2];
    const float* lf    = (const float*)d_in[3];
    const float* W1    = (const float*)d_in[4];
    const float* b1    = (const float*)d_in[5];
    const float* W2    = (const float*)d_in[6];
    const float* b2    = (const float*)d_in[7];
    float* out = (float*)d_out;

    const int N = in_sizes[2];
    const int nTiles = (N + TILE_M - 1) / TILE_M;

    int nsm = 148;
    cudaDeviceGetAttribute(&nsm, cudaDevAttrMultiProcessorCount, 0);
    if (nsm <= 0) nsm = 148;

    cudaFuncSetAttribute(k_main, cudaFuncAttributeMaxDynamicSharedMemorySize,
                         SMEM_BYTES);

    k_init  <<<(B_GRAPHS * D_OUT + TPB - 1) / TPB, TPB>>>(N);
    k_bounds<<<(N + TPB - 1) / TPB, TPB>>>(batch, N);
    k_fill  <<<1, 1>>>();
    k_graph <<<B_GRAPHS, TPB>>>(x, pos, batch, lf, W1, b1, out, N);
    k_main  <<<nsm, TPB, SMEM_BYTES>>>(x, pos, batch, W1, W2, b2, N, nTiles);
    k_out   <<<(B_GRAPHS * D_OUT + TPB - 1) / TPB, TPB>>>(out);
}